// round 1
// baseline (speedup 1.0000x reference)
#include <cuda_runtime.h>
#include <math.h>

// Problem sizes (fixed by the reference)
#define BSZ  8
#define LSZ  2048
#define DMSZ 1024
#define DHSZ 1024
#define MSZ  (BSZ * LSZ)   // 16384 rows (b,l flattened)

// Scratch: __device__ globals (allocation-free rule). 3 x 64MB.
__device__ float g_Abar[(size_t)MSZ * DHSZ];
__device__ float g_Bbar[(size_t)MSZ * DHSZ];
__device__ float g_H   [(size_t)MSZ * DHSZ];

// ---------------------------------------------------------------------------
// Kernel 1: fused dual GEMM + SSM parameterization epilogue.
//   T1 = x @ dw^T + db   -> delta = softplus(T1)
//   T2 = x @ Bw^T + Bb
//   A_bar = exp(delta * A), B_bar = delta * T2
// x: [M, DM] row-major; dw,Bw: [DH, DM] row-major (K-contiguous).
// Tiling: BM=128, BN=64, BK=16, 256 threads, 8x4 per-thread, dual accumulators.
// ---------------------------------------------------------------------------
__global__ __launch_bounds__(256) void gemm_bd_kernel(
    const float* __restrict__ x,
    const float* __restrict__ dw, const float* __restrict__ dbias,
    const float* __restrict__ Bw, const float* __restrict__ Bb,
    const float* __restrict__ Avec)
{
    const int BM = 128, BN = 64, BK = 16;
    __shared__ float As[BK][BM];
    __shared__ float Ds[BK][BN];
    __shared__ float Bs[BK][BN];

    const int m0 = blockIdx.y * BM;
    const int n0 = blockIdx.x * BN;
    const int t  = threadIdx.x;
    const int tx = t & 15;       // 0..15 -> n
    const int ty = t >> 4;       // 0..15 -> m

    float acc1[8][4];
    float acc2[8][4];
#pragma unroll
    for (int i = 0; i < 8; i++)
#pragma unroll
        for (int j = 0; j < 4; j++) { acc1[i][j] = 0.f; acc2[i][j] = 0.f; }

    for (int k0 = 0; k0 < DMSZ; k0 += BK) {
        // Load x tile 128x16, transposed into As[k][m]
#pragma unroll
        for (int it = 0; it < 2; it++) {
            int idx = t + it * 256;          // 0..511 float4 slots
            int row = idx >> 2;              // 0..127
            int kq  = idx & 3;               // 0..3
            float4 v = *(const float4*)&x[(size_t)(m0 + row) * DMSZ + k0 + kq * 4];
            As[kq * 4 + 0][row] = v.x;
            As[kq * 4 + 1][row] = v.y;
            As[kq * 4 + 2][row] = v.z;
            As[kq * 4 + 3][row] = v.w;
        }
        // Load dw / Bw tiles 64x16, transposed into Ds/Bs[k][n]
        {
            int row = t >> 2;                // 0..63
            int kq  = t & 3;                 // 0..3
            float4 v = *(const float4*)&dw[(size_t)(n0 + row) * DMSZ + k0 + kq * 4];
            Ds[kq * 4 + 0][row] = v.x;
            Ds[kq * 4 + 1][row] = v.y;
            Ds[kq * 4 + 2][row] = v.z;
            Ds[kq * 4 + 3][row] = v.w;
            float4 w = *(const float4*)&Bw[(size_t)(n0 + row) * DMSZ + k0 + kq * 4];
            Bs[kq * 4 + 0][row] = w.x;
            Bs[kq * 4 + 1][row] = w.y;
            Bs[kq * 4 + 2][row] = w.z;
            Bs[kq * 4 + 3][row] = w.w;
        }
        __syncthreads();

#pragma unroll
        for (int kk = 0; kk < BK; kk++) {
            const float4* ap = (const float4*)&As[kk][ty * 8];
            float4 a0 = ap[0], a1 = ap[1];
            float4 d4 = *(const float4*)&Ds[kk][tx * 4];
            float4 b4 = *(const float4*)&Bs[kk][tx * 4];
            float a[8] = {a0.x, a0.y, a0.z, a0.w, a1.x, a1.y, a1.z, a1.w};
            float dv[4] = {d4.x, d4.y, d4.z, d4.w};
            float bv[4] = {b4.x, b4.y, b4.z, b4.w};
#pragma unroll
            for (int i = 0; i < 8; i++)
#pragma unroll
                for (int j = 0; j < 4; j++) {
                    acc1[i][j] = fmaf(a[i], dv[j], acc1[i][j]);
                    acc2[i][j] = fmaf(a[i], bv[j], acc2[i][j]);
                }
        }
        __syncthreads();
    }

    // Epilogue: softplus / exp / scale, vectorized stores
    float dbv[4], av[4], bbv[4];
#pragma unroll
    for (int j = 0; j < 4; j++) {
        int n = n0 + tx * 4 + j;
        dbv[j] = dbias[n];
        av[j]  = Avec[n];
        bbv[j] = Bb[n];
    }
#pragma unroll
    for (int i = 0; i < 8; i++) {
        int m = m0 + ty * 8 + i;
        float4 oa, ob;
        float* pa = (float*)&oa;
        float* pb = (float*)&ob;
#pragma unroll
        for (int j = 0; j < 4; j++) {
            float t1 = acc1[i][j] + dbv[j];
            float delta = (t1 > 20.f) ? t1 : log1pf(expf(t1));
            pa[j] = expf(delta * av[j]);
            pb[j] = delta * (acc2[i][j] + bbv[j]);
        }
        size_t off = (size_t)m * DHSZ + n0 + tx * 4;
        *(float4*)&g_Abar[off] = oa;
        *(float4*)&g_Bbar[off] = ob;
    }
}

// ---------------------------------------------------------------------------
// Kernel 2: linear recurrence h_t = A_bar_t * h_{t-1} + B_bar_t
// One thread per (b, h) channel; unroll-8 batched loads for MLP.
// ---------------------------------------------------------------------------
__global__ __launch_bounds__(32) void scan_kernel()
{
    int c = blockIdx.x * 32 + threadIdx.x;   // 0..8191
    int b = c >> 10;
    int h = c & (DHSZ - 1);
    size_t base = (size_t)b * LSZ * DHSZ + h;

    float hp = 0.f;
    for (int l0 = 0; l0 < LSZ; l0 += 8) {
        float av[8], bv[8];
#pragma unroll
        for (int u = 0; u < 8; u++) {
            size_t off = base + (size_t)(l0 + u) * DHSZ;
            av[u] = g_Abar[off];
            bv[u] = g_Bbar[off];
        }
#pragma unroll
        for (int u = 0; u < 8; u++) {
            hp = fmaf(av[u], hp, bv[u]);
            g_H[base + (size_t)(l0 + u) * DHSZ] = hp;
        }
    }
}

// ---------------------------------------------------------------------------
// Kernel 3: out = h @ Cw^T + x @ Dw^T + Cb + Db
// Cw: [DM, DH], Dw: [DM, DM], both K-contiguous. Two K=1024 passes, one acc.
// ---------------------------------------------------------------------------
__global__ __launch_bounds__(256) void gemm_out_kernel(
    const float* __restrict__ x,
    const float* __restrict__ Cw, const float* __restrict__ Cb,
    const float* __restrict__ Dw, const float* __restrict__ Db,
    float* __restrict__ out)
{
    const int BM = 128, BN = 64, BK = 16;
    __shared__ float As[BK][BM];
    __shared__ float Bs[BK][BN];

    const int m0 = blockIdx.y * BM;
    const int n0 = blockIdx.x * BN;
    const int t  = threadIdx.x;
    const int tx = t & 15;
    const int ty = t >> 4;

    float acc[8][4];
#pragma unroll
    for (int i = 0; i < 8; i++)
#pragma unroll
        for (int j = 0; j < 4; j++) acc[i][j] = 0.f;

    for (int pass = 0; pass < 2; pass++) {
        const float* Ag = pass ? x  : g_H;
        const float* Bg = pass ? Dw : Cw;

        for (int k0 = 0; k0 < 1024; k0 += BK) {
#pragma unroll
            for (int it = 0; it < 2; it++) {
                int idx = t + it * 256;
                int row = idx >> 2;
                int kq  = idx & 3;
                float4 v = *(const float4*)&Ag[(size_t)(m0 + row) * 1024 + k0 + kq * 4];
                As[kq * 4 + 0][row] = v.x;
                As[kq * 4 + 1][row] = v.y;
                As[kq * 4 + 2][row] = v.z;
                As[kq * 4 + 3][row] = v.w;
            }
            {
                int row = t >> 2;
                int kq  = t & 3;
                float4 v = *(const float4*)&Bg[(size_t)(n0 + row) * 1024 + k0 + kq * 4];
                Bs[kq * 4 + 0][row] = v.x;
                Bs[kq * 4 + 1][row] = v.y;
                Bs[kq * 4 + 2][row] = v.z;
                Bs[kq * 4 + 3][row] = v.w;
            }
            __syncthreads();

#pragma unroll
            for (int kk = 0; kk < BK; kk++) {
                const float4* ap = (const float4*)&As[kk][ty * 8];
                float4 a0 = ap[0], a1 = ap[1];
                float4 b4 = *(const float4*)&Bs[kk][tx * 4];
                float a[8] = {a0.x, a0.y, a0.z, a0.w, a1.x, a1.y, a1.z, a1.w};
                float bv[4] = {b4.x, b4.y, b4.z, b4.w};
#pragma unroll
                for (int i = 0; i < 8; i++)
#pragma unroll
                    for (int j = 0; j < 4; j++)
                        acc[i][j] = fmaf(a[i], bv[j], acc[i][j]);
            }
            __syncthreads();
        }
    }

    float biasv[4];
#pragma unroll
    for (int j = 0; j < 4; j++) {
        int n = n0 + tx * 4 + j;
        biasv[j] = Cb[n] + Db[n];
    }
#pragma unroll
    for (int i = 0; i < 8; i++) {
        int m = m0 + ty * 8 + i;
        float4 o;
        float* po = (float*)&o;
#pragma unroll
        for (int j = 0; j < 4; j++) po[j] = acc[i][j] + biasv[j];
        *(float4*)&out[(size_t)m * DMSZ + n0 + tx * 4] = o;
    }
}

// ---------------------------------------------------------------------------
// Input order (metadata): 0:x 1:A 2:Bw 3:Bb 4:Cw 5:Cb 6:Dw 7:Db 8:dw 9:db
// ---------------------------------------------------------------------------
extern "C" void kernel_launch(void* const* d_in, const int* in_sizes, int n_in,
                              void* d_out, int out_size)
{
    const float* x    = (const float*)d_in[0];
    const float* Avec = (const float*)d_in[1];
    const float* Bw   = (const float*)d_in[2];
    const float* Bb   = (const float*)d_in[3];
    const float* Cw   = (const float*)d_in[4];
    const float* Cb   = (const float*)d_in[5];
    const float* Dw   = (const float*)d_in[6];
    const float* Db   = (const float*)d_in[7];
    const float* dw   = (const float*)d_in[8];
    const float* db   = (const float*)d_in[9];
    float* out = (float*)d_out;

    dim3 g1(DHSZ / 64, MSZ / 128);
    gemm_bd_kernel<<<g1, 256>>>(x, dw, db, Bw, Bb, Avec);

    scan_kernel<<<(BSZ * DHSZ) / 32, 32>>>();

    dim3 g3(DMSZ / 64, MSZ / 128);
    gemm_out_kernel<<<g3, 256>>>(x, Cw, Cb, Dw, Db, out);
}

// round 4
// speedup vs baseline: 2.5037x; 2.5037x over previous
#include <cuda_runtime.h>
#include <cuda_bf16.h>
#include <cstdint>

#define BSZ  8
#define LSZ  2048
#define DMSZ 1024
#define DHSZ 1024
#define MSZ  (BSZ * LSZ)   // 16384

// ---------------- scratch (__device__ globals; allocation-free rule) -------
__device__ __nv_bfloat16 g_xhi[(size_t)MSZ * DMSZ];
__device__ __nv_bfloat16 g_xlo[(size_t)MSZ * DMSZ];
__device__ __nv_bfloat16 g_dwhi[DHSZ * DMSZ], g_dwlo[DHSZ * DMSZ];
__device__ __nv_bfloat16 g_Bwhi[DHSZ * DMSZ], g_Bwlo[DHSZ * DMSZ];
__device__ __nv_bfloat16 g_Cwhi[DMSZ * DHSZ], g_Cwlo[DMSZ * DHSZ];
__device__ __nv_bfloat16 g_Dwhi[DMSZ * DMSZ], g_Dwlo[DMSZ * DMSZ];
__device__ float g_Abar[(size_t)MSZ * DHSZ];
__device__ float g_Bbar[(size_t)MSZ * DHSZ];
__device__ __nv_bfloat16 g_Hhi[(size_t)MSZ * DHSZ];
__device__ __nv_bfloat16 g_Hlo[(size_t)MSZ * DHSZ];

// ---------------- helpers --------------------------------------------------
__device__ __forceinline__ uint32_t smem_u32(const void* p) {
    uint32_t a;
    asm("{ .reg .u64 t; cvta.to.shared.u64 t, %1; cvt.u32.u64 %0, t; }"
        : "=r"(a) : "l"(p));
    return a;
}

// SMEM tile layout: rows of 32 bf16 = 64B = 4 chunks of 16B.
// chunk' = chunk ^ ((row>>1)&3)  -> conflict-free for ldmatrix + stores.
__device__ __forceinline__ uint32_t sw_chunk_off(int r, int c) {
    return (uint32_t)(((r << 2) | (c ^ ((r >> 1) & 3))) << 4);
}

__device__ __forceinline__ void ldsm4(uint32_t* d, uint32_t addr) {
    asm volatile("ldmatrix.sync.aligned.m8n8.x4.shared.b16 {%0,%1,%2,%3}, [%4];"
                 : "=r"(d[0]), "=r"(d[1]), "=r"(d[2]), "=r"(d[3]) : "r"(addr));
}

__device__ __forceinline__ void mma16816(float* c, const uint32_t* a, const uint32_t* b) {
    asm volatile(
        "mma.sync.aligned.m16n8k16.row.col.f32.bf16.bf16.f32 "
        "{%0,%1,%2,%3}, {%4,%5,%6,%7}, {%8,%9}, {%0,%1,%2,%3};"
        : "+f"(c[0]), "+f"(c[1]), "+f"(c[2]), "+f"(c[3])
        : "r"(a[0]), "r"(a[1]), "r"(a[2]), "r"(a[3]), "r"(b[0]), "r"(b[1]));
}

// A-fragment ldmatrix address: m16k16 tile at (mrow, chunk c0..c0+1)
__device__ __forceinline__ uint32_t addrA(uint32_t sbase, int mrow, int c0) {
    int l = threadIdx.x & 31;
    int r = mrow + (l & 15);
    int c = c0 + (l >> 4);
    return sbase + sw_chunk_off(r, c);
}
// B-fragment ldmatrix address: two n8k16 tiles at (nrow..nrow+15, chunk c0..c0+1)
__device__ __forceinline__ uint32_t addrB(uint32_t sbase, int nrow, int c0) {
    int l = threadIdx.x & 31;
    int r = nrow + (l & 7) + ((l >> 4) << 3);
    int c = c0 + ((l >> 3) & 1);
    return sbase + sw_chunk_off(r, c);
}

template <int ROWS>
__device__ __forceinline__ void load_tile_async(uint32_t sbase,
                                                const __nv_bfloat16* __restrict__ g,
                                                int row0, int kb)
{
    int t = threadIdx.x;
#pragma unroll
    for (int i = 0; i < (ROWS * 4) / 256; i++) {
        int idx = i * 256 + t;
        int r = idx >> 2;
        int c = idx & 3;
        const char* src = (const char*)(g + (size_t)(row0 + r) * 1024 + kb) + c * 16;
        uint32_t dst = sbase + sw_chunk_off(r, c);
        asm volatile("cp.async.cg.shared.global [%0], [%1], 16;"
                     :: "r"(dst), "l"(src) : "memory");
    }
}
#define CP_COMMIT()  asm volatile("cp.async.commit_group;" ::: "memory")
#define CP_WAIT(n)   asm volatile("cp.async.wait_group %0;" :: "n"(n) : "memory")

// ---------------- prep: fp32 -> bf16 hi/lo split ---------------------------
__global__ __launch_bounds__(256) void convert_kernel(
    const float* __restrict__ src, __nv_bfloat16* __restrict__ hi,
    __nv_bfloat16* __restrict__ lo, int n4)
{
    int i = blockIdx.x * 256 + threadIdx.x;
    if (i >= n4) return;
    float4 v = ((const float4*)src)[i];
    __nv_bfloat16 h0 = __float2bfloat16_rn(v.x);
    __nv_bfloat16 h1 = __float2bfloat16_rn(v.y);
    __nv_bfloat16 h2 = __float2bfloat16_rn(v.z);
    __nv_bfloat16 h3 = __float2bfloat16_rn(v.w);
    __nv_bfloat16 l0 = __float2bfloat16_rn(v.x - __bfloat162float(h0));
    __nv_bfloat16 l1 = __float2bfloat16_rn(v.y - __bfloat162float(h1));
    __nv_bfloat16 l2 = __float2bfloat16_rn(v.z - __bfloat162float(h2));
    __nv_bfloat16 l3 = __float2bfloat16_rn(v.w - __bfloat162float(h3));
    __nv_bfloat162* h2p = (__nv_bfloat162*)(hi + (size_t)i * 4);
    __nv_bfloat162* l2p = (__nv_bfloat162*)(lo + (size_t)i * 4);
    h2p[0] = __halves2bfloat162(h0, h1);
    h2p[1] = __halves2bfloat162(h2, h3);
    l2p[0] = __halves2bfloat162(l0, l1);
    l2p[1] = __halves2bfloat162(l2, l3);
}

// ---------------- kernel 1: dual GEMM (x@dw^T, x@Bw^T) + SSM epilogue ------
// CTA tile 128(M) x 64(N). 8 warps: 4(m) x 2(n); warp tile 32x32.
// Stage (32KB): Ah 0, Al 8192, W1h 16384, W1l 20480, W2h 24576, W2l 28672.
__global__ __launch_bounds__(256, 1)
void gemm1_kernel(const float* __restrict__ dbias, const float* __restrict__ Bb,
                  const float* __restrict__ Avec)
{
    extern __shared__ char smem[];
    uint32_t sb = smem_u32(smem);
    const int t = threadIdx.x, wid = t >> 5, lane = t & 31;
    const int m0 = blockIdx.y * 128, n0 = blockIdx.x * 64;
    const int wm = (wid & 3) * 32;
    const int wn = (wid >> 2) * 32;

    float acc1[2][4][4], acc2[2][4][4];
#pragma unroll
    for (int i = 0; i < 2; i++)
#pragma unroll
        for (int j = 0; j < 4; j++)
#pragma unroll
            for (int q = 0; q < 4; q++) { acc1[i][j][q] = 0.f; acc2[i][j][q] = 0.f; }

    // prologue
    {
        uint32_t st = sb;
        load_tile_async<128>(st,          g_xhi,  m0, 0);
        load_tile_async<128>(st + 8192,   g_xlo,  m0, 0);
        load_tile_async<64> (st + 16384,  g_dwhi, n0, 0);
        load_tile_async<64> (st + 20480,  g_dwlo, n0, 0);
        load_tile_async<64> (st + 24576,  g_Bwhi, n0, 0);
        load_tile_async<64> (st + 28672,  g_Bwlo, n0, 0);
        CP_COMMIT();
    }

    for (int k = 0; k < 32; k++) {
        if (k + 1 < 32) {
            uint32_t st = sb + ((k + 1) & 1) * 32768;
            int kb = (k + 1) * 32;
            load_tile_async<128>(st,          g_xhi,  m0, kb);
            load_tile_async<128>(st + 8192,   g_xlo,  m0, kb);
            load_tile_async<64> (st + 16384,  g_dwhi, n0, kb);
            load_tile_async<64> (st + 20480,  g_dwlo, n0, kb);
            load_tile_async<64> (st + 24576,  g_Bwhi, n0, kb);
            load_tile_async<64> (st + 28672,  g_Bwlo, n0, kb);
            CP_COMMIT();
            CP_WAIT(1);
        } else {
            CP_WAIT(0);
        }
        __syncthreads();

        uint32_t st = sb + (k & 1) * 32768;
#pragma unroll
        for (int kk = 0; kk < 2; kk++) {
            int c0 = kk * 2;
            uint32_t ah[2][4], al[2][4];
#pragma unroll
            for (int mt = 0; mt < 2; mt++) {
                ldsm4(ah[mt], addrA(st,        wm + mt * 16, c0));
                ldsm4(al[mt], addrA(st + 8192, wm + mt * 16, c0));
            }
            uint32_t b1h[8], b1l[8], b2h[8], b2l[8];
            ldsm4(b1h,     addrB(st + 16384, wn,      c0));
            ldsm4(b1h + 4, addrB(st + 16384, wn + 16, c0));
            ldsm4(b1l,     addrB(st + 20480, wn,      c0));
            ldsm4(b1l + 4, addrB(st + 20480, wn + 16, c0));
            ldsm4(b2h,     addrB(st + 24576, wn,      c0));
            ldsm4(b2h + 4, addrB(st + 24576, wn + 16, c0));
            ldsm4(b2l,     addrB(st + 28672, wn,      c0));
            ldsm4(b2l + 4, addrB(st + 28672, wn + 16, c0));
#pragma unroll
            for (int mt = 0; mt < 2; mt++)
#pragma unroll
                for (int nt = 0; nt < 4; nt++) {
                    mma16816(acc1[mt][nt], ah[mt], &b1h[nt * 2]);
                    mma16816(acc1[mt][nt], ah[mt], &b1l[nt * 2]);
                    mma16816(acc1[mt][nt], al[mt], &b1h[nt * 2]);
                    mma16816(acc2[mt][nt], ah[mt], &b2h[nt * 2]);
                    mma16816(acc2[mt][nt], ah[mt], &b2l[nt * 2]);
                    mma16816(acc2[mt][nt], al[mt], &b2h[nt * 2]);
                }
        }
        __syncthreads();
    }

    // epilogue: delta = softplus(T1 + db); Abar = exp(delta*A); Bbar = delta*(T2 + Bb)
    const int lr = lane >> 2, lc = lane & 3;
    float dbv[4][2], avv[4][2], bbv[4][2];
#pragma unroll
    for (int nt = 0; nt < 4; nt++)
#pragma unroll
        for (int j = 0; j < 2; j++) {
            int n = n0 + wn + nt * 8 + lc * 2 + j;
            dbv[nt][j] = __ldg(&dbias[n]);
            avv[nt][j] = __ldg(&Avec[n]);
            bbv[nt][j] = __ldg(&Bb[n]);
        }
#pragma unroll
    for (int mt = 0; mt < 2; mt++)
#pragma unroll
        for (int half = 0; half < 2; half++) {
            int m = m0 + wm + mt * 16 + half * 8 + lr;
            size_t rowo = (size_t)m * DHSZ;
#pragma unroll
            for (int nt = 0; nt < 4; nt++) {
                int n = n0 + wn + nt * 8 + lc * 2;
                float2 oa, ob;
#pragma unroll
                for (int j = 0; j < 2; j++) {
                    float t1 = acc1[mt][nt][half * 2 + j] + dbv[nt][j];
                    float e = __expf(-fabsf(t1));
                    float delta = fmaxf(t1, 0.f) + __logf(1.f + e);
                    float a = __expf(delta * avv[nt][j]);
                    float b = delta * (acc2[mt][nt][half * 2 + j] + bbv[nt][j]);
                    if (j == 0) { oa.x = a; ob.x = b; } else { oa.y = a; ob.y = b; }
                }
                *(float2*)&g_Abar[rowo + n] = oa;
                *(float2*)&g_Bbar[rowo + n] = ob;
            }
        }
}

// ---------------- kernel 2: linear recurrence scan -------------------------
__global__ __launch_bounds__(256) void scan_kernel()
{
    int c = blockIdx.x * 256 + threadIdx.x;   // 0..8191
    int b = c >> 10;
    int h = c & (DHSZ - 1);
    size_t base = (size_t)b * LSZ * DHSZ + h;

    float hp = 0.f;
    for (int l0 = 0; l0 < LSZ; l0 += 16) {
        float av[16], bv[16];
#pragma unroll
        for (int u = 0; u < 16; u++) {
            size_t o = base + (size_t)(l0 + u) * DHSZ;
            av[u] = g_Abar[o];
            bv[u] = g_Bbar[o];
        }
#pragma unroll
        for (int u = 0; u < 16; u++) {
            hp = fmaf(av[u], hp, bv[u]);
            size_t o = base + (size_t)(l0 + u) * DHSZ;
            __nv_bfloat16 hh = __float2bfloat16_rn(hp);
            g_Hhi[o] = hh;
            g_Hlo[o] = __float2bfloat16_rn(hp - __bfloat162float(hh));
        }
    }
}

// ---------------- kernel 3: out = h@Cw^T + x@Dw^T + Cb + Db ----------------
// CTA tile 128x128. 8 warps: 2(m) x 4(n); warp tile 64x32.
// Stage (32KB): Ah 0, Al 8192, Wh 16384, Wl 24576.
__global__ __launch_bounds__(256, 1)
void gemm3_kernel(const float* __restrict__ Cb, const float* __restrict__ Db,
                  float* __restrict__ out)
{
    extern __shared__ char smem[];
    uint32_t sb = smem_u32(smem);
    const int t = threadIdx.x, wid = t >> 5, lane = t & 31;
    const int m0 = blockIdx.y * 128, n0 = blockIdx.x * 128;
    const int wm = (wid & 1) * 64;
    const int wn = (wid >> 1) * 32;

    float acc[4][4][4];
#pragma unroll
    for (int i = 0; i < 4; i++)
#pragma unroll
        for (int j = 0; j < 4; j++)
#pragma unroll
            for (int q = 0; q < 4; q++) acc[i][j][q] = 0.f;

    auto issue_stage = [&](int s, int kidx) {
        const __nv_bfloat16 *Ah, *Al, *Wh, *Wl;
        if (kidx < 32) { Ah = g_Hhi; Al = g_Hlo; Wh = g_Cwhi; Wl = g_Cwlo; }
        else           { Ah = g_xhi; Al = g_xlo; Wh = g_Dwhi; Wl = g_Dwlo; }
        int kb = (kidx & 31) * 32;
        uint32_t st = sb + s * 32768;
        load_tile_async<128>(st,          Ah, m0, kb);
        load_tile_async<128>(st + 8192,   Al, m0, kb);
        load_tile_async<128>(st + 16384,  Wh, n0, kb);
        load_tile_async<128>(st + 24576,  Wl, n0, kb);
    };

    issue_stage(0, 0);
    CP_COMMIT();

    for (int k = 0; k < 64; k++) {
        if (k + 1 < 64) { issue_stage((k + 1) & 1, k + 1); CP_COMMIT(); CP_WAIT(1); }
        else            { CP_WAIT(0); }
        __syncthreads();

        uint32_t st = sb + (k & 1) * 32768;
#pragma unroll
        for (int kk = 0; kk < 2; kk++) {
            int c0 = kk * 2;
            uint32_t ah[4][4], al[4][4];
#pragma unroll
            for (int mt = 0; mt < 4; mt++) {
                ldsm4(ah[mt], addrA(st,        wm + mt * 16, c0));
                ldsm4(al[mt], addrA(st + 8192, wm + mt * 16, c0));
            }
            uint32_t bh[8], bl[8];
            ldsm4(bh,     addrB(st + 16384, wn,      c0));
            ldsm4(bh + 4, addrB(st + 16384, wn + 16, c0));
            ldsm4(bl,     addrB(st + 24576, wn,      c0));
            ldsm4(bl + 4, addrB(st + 24576, wn + 16, c0));
#pragma unroll
            for (int mt = 0; mt < 4; mt++)
#pragma unroll
                for (int nt = 0; nt < 4; nt++) {
                    mma16816(acc[mt][nt], ah[mt], &bh[nt * 2]);
                    mma16816(acc[mt][nt], ah[mt], &bl[nt * 2]);
                    mma16816(acc[mt][nt], al[mt], &bh[nt * 2]);
                }
        }
        __syncthreads();
    }

    const int lr = lane >> 2, lc = lane & 3;
    float biasv[4][2];
#pragma unroll
    for (int nt = 0; nt < 4; nt++)
#pragma unroll
        for (int j = 0; j < 2; j++) {
            int n = n0 + wn + nt * 8 + lc * 2 + j;
            biasv[nt][j] = __ldg(&Cb[n]) + __ldg(&Db[n]);
        }
#pragma unroll
    for (int mt = 0; mt < 4; mt++)
#pragma unroll
        for (int half = 0; half < 2; half++) {
            int m = m0 + wm + mt * 16 + half * 8 + lr;
            size_t rowo = (size_t)m * DMSZ;
#pragma unroll
            for (int nt = 0; nt < 4; nt++) {
                int n = n0 + wn + nt * 8 + lc * 2;
                float2 o;
                o.x = acc[mt][nt][half * 2 + 0] + biasv[nt][0];
                o.y = acc[mt][nt][half * 2 + 1] + biasv[nt][1];
                *(float2*)&out[rowo + n] = o;
            }
        }
}

// ---------------- launch ---------------------------------------------------
// Inputs: 0:x 1:A 2:Bw 3:Bb 4:Cw 5:Cb 6:Dw 7:Db 8:dw 9:db
extern "C" void kernel_launch(void* const* d_in, const int* in_sizes, int n_in,
                              void* d_out, int out_size)
{
    const float* x    = (const float*)d_in[0];
    const float* Avec = (const float*)d_in[1];
    const float* Bw   = (const float*)d_in[2];
    const float* Bb   = (const float*)d_in[3];
    const float* Cw   = (const float*)d_in[4];
    const float* Cb   = (const float*)d_in[5];
    const float* Dw   = (const float*)d_in[6];
    const float* Db   = (const float*)d_in[7];
    const float* dw   = (const float*)d_in[8];
    const float* db   = (const float*)d_in[9];
    float* out = (float*)d_out;

    void *xhi, *xlo, *dwhi, *dwlo, *bwhi, *bwlo, *cwhi, *cwlo, *Dwhi, *Dwlo;
    cudaGetSymbolAddress(&xhi, g_xhi);   cudaGetSymbolAddress(&xlo, g_xlo);
    cudaGetSymbolAddress(&dwhi, g_dwhi); cudaGetSymbolAddress(&dwlo, g_dwlo);
    cudaGetSymbolAddress(&bwhi, g_Bwhi); cudaGetSymbolAddress(&bwlo, g_Bwlo);
    cudaGetSymbolAddress(&cwhi, g_Cwhi); cudaGetSymbolAddress(&cwlo, g_Cwlo);
    cudaGetSymbolAddress(&Dwhi, g_Dwhi); cudaGetSymbolAddress(&Dwlo, g_Dwlo);

    cudaFuncSetAttribute(gemm1_kernel, cudaFuncAttributeMaxDynamicSharedMemorySize, 65536);
    cudaFuncSetAttribute(gemm3_kernel, cudaFuncAttributeMaxDynamicSharedMemorySize, 65536);

    int nx4 = (MSZ * DMSZ) / 4;
    int nw4 = (DHSZ * DMSZ) / 4;
    convert_kernel<<<nx4 / 256, 256>>>(x,  (__nv_bfloat16*)xhi,  (__nv_bfloat16*)xlo,  nx4);
    convert_kernel<<<nw4 / 256, 256>>>(dw, (__nv_bfloat16*)dwhi, (__nv_bfloat16*)dwlo, nw4);
    convert_kernel<<<nw4 / 256, 256>>>(Bw, (__nv_bfloat16*)bwhi, (__nv_bfloat16*)bwlo, nw4);
    convert_kernel<<<nw4 / 256, 256>>>(Cw, (__nv_bfloat16*)cwhi, (__nv_bfloat16*)cwlo, nw4);
    convert_kernel<<<nw4 / 256, 256>>>(Dw, (__nv_bfloat16*)Dwhi, (__nv_bfloat16*)Dwlo, nw4);

    dim3 g1(DHSZ / 64, MSZ / 128);    // (16, 128)
    gemm1_kernel<<<g1, 256, 65536>>>(db, Bb, Avec);

    scan_kernel<<<(BSZ * DHSZ) / 256, 256>>>();

    dim3 g3(DMSZ / 128, MSZ / 128);   // (8, 128)
    gemm3_kernel<<<g3, 256, 65536>>>(Cb, Db, out);
}